// round 1
// baseline (speedup 1.0000x reference)
#include <cuda_runtime.h>

#define NB 32
#define NL 128
#define ND 512
#define NROWS (NB*NL)   // 4096

// ---- scratch (static device arrays; no allocation) ----
__device__ float g_wq_new[NROWS*ND];  // new_obs@Wq + bq
__device__ float g_wq_cur[NROWS*ND];  // current@Wq + bq
__device__ float g_uh_new[NROWS*ND];  // new_obs@Wc
__device__ float g_uh_cur[NROWS*ND];  // current@Wc
__device__ float g_c1[NROWS*ND];      // context for a1 (source=new_obs, memory=current)
__device__ float g_c2[NROWS*ND];      // context for a2

__device__ __forceinline__ float tanh_apx(float x){
    float y;
    asm("tanh.approx.f32 %0, %1;" : "=f"(y) : "f"(x));
    return y;
}

// ============================================================
// Projection GEMM: C[4096,512] = A[4096,512] @ W[512,512] (+bias)
// 64x64 tile, BK=16, 256 threads, 4x4 per thread.
// ============================================================
__global__ void __launch_bounds__(256) proj_gemm(
    const float* __restrict__ A, const float* __restrict__ W,
    const float* __restrict__ bias, int outsel)
{
    __shared__ float As[16][68];   // [k][m], pad 68 -> conflict-free transpose store, 16B-aligned rows
    __shared__ float Bs[16][64];   // [k][n]
    float* C = (outsel==0)?g_wq_new:(outsel==1)?g_wq_cur:(outsel==2)?g_uh_new:g_uh_cur;
    const int K = ND;
    int tid = threadIdx.x;
    int m0 = blockIdx.x*64, n0 = blockIdx.y*64;
    int tx = tid & 15, ty = tid >> 4;
    int lr = tid >> 2, lk = (tid & 3) * 4;

    float acc[4][4];
    #pragma unroll
    for (int i=0;i<4;i++)
        #pragma unroll
        for (int j=0;j<4;j++) acc[i][j]=0.f;

    for (int k0=0; k0<K; k0+=16){
        float4 av = *(const float4*)(A + (size_t)(m0+lr)*K + k0 + lk);
        float4 wv = *(const float4*)(W + (size_t)(k0+ty)*ND + n0 + tx*4);
        As[lk+0][lr]=av.x; As[lk+1][lr]=av.y; As[lk+2][lr]=av.z; As[lk+3][lr]=av.w;
        *(float4*)&Bs[ty][tx*4] = wv;
        __syncthreads();
        #pragma unroll
        for (int k=0;k<16;k++){
            float4 a = *(const float4*)&As[k][ty*4];
            float4 b = *(const float4*)&Bs[k][tx*4];
            acc[0][0]+=a.x*b.x; acc[0][1]+=a.x*b.y; acc[0][2]+=a.x*b.z; acc[0][3]+=a.x*b.w;
            acc[1][0]+=a.y*b.x; acc[1][1]+=a.y*b.y; acc[1][2]+=a.y*b.z; acc[1][3]+=a.y*b.w;
            acc[2][0]+=a.z*b.x; acc[2][1]+=a.z*b.y; acc[2][2]+=a.z*b.z; acc[2][3]+=a.z*b.w;
            acc[3][0]+=a.w*b.x; acc[3][1]+=a.w*b.y; acc[3][2]+=a.w*b.z; acc[3][3]+=a.w*b.w;
        }
        __syncthreads();
    }

    float b0=0.f,b1=0.f,b2=0.f,b3=0.f;
    if (bias){
        b0=bias[n0+tx*4+0]; b1=bias[n0+tx*4+1];
        b2=bias[n0+tx*4+2]; b3=bias[n0+tx*4+3];
    }
    #pragma unroll
    for (int i=0;i<4;i++){
        float4 r;
        r.x=acc[i][0]+b0; r.y=acc[i][1]+b1; r.z=acc[i][2]+b2; r.w=acc[i][3]+b3;
        *(float4*)(C + (size_t)(m0+ty*4+i)*ND + n0 + tx*4) = r;
    }
}

// ============================================================
// Fused attention: scores (v.tanh(wq+uh)) -> softmax -> context.
// Block = (b, 8-row t-tile, direction). 256 threads = 8 warps,
// warp w owns t = t0+w for scores/softmax; all threads cooperate
// on the context BMM.
// ============================================================
__global__ void __launch_bounds__(256) attn_kernel(
    const float* __restrict__ cur, const float* __restrict__ no,
    const float* __restrict__ v)
{
    __shared__ float sc[8][128];    // raw scores [t][s]
    __shared__ float pm[128][8];    // probabilities [s][t] (transposed for phase 3)

    int dir = blockIdx.z;
    int bb  = blockIdx.y;
    int t0  = blockIdx.x * 8;
    const float* wq  = dir ? g_wq_cur : g_wq_new;
    const float* uh  = dir ? g_uh_new : g_uh_cur;
    const float* mem = dir ? no       : cur;
    float*       cO  = dir ? g_c2     : g_c1;

    int tid = threadIdx.x, w = tid >> 5, lane = tid & 31;

    // ---- phase 1: scores. warp w <-> row t0+w; lane owns 16 d-slots.
    float4 v4[4], q4[4];
    {
        const float* wrow = wq + (size_t)(bb*NL + t0 + w)*ND;
        #pragma unroll
        for (int i=0;i<4;i++){
            v4[i] = *(const float4*)(v    + lane*4 + 128*i);
            q4[i] = *(const float4*)(wrow + lane*4 + 128*i);
        }
    }
    for (int s=0; s<NL; s++){
        const float* urow = uh + (size_t)(bb*NL + s)*ND;
        float acc = 0.f;
        #pragma unroll
        for (int i=0;i<4;i++){
            float4 u = *(const float4*)(urow + lane*4 + 128*i);
            acc += v4[i].x * tanh_apx(q4[i].x + u.x);
            acc += v4[i].y * tanh_apx(q4[i].y + u.y);
            acc += v4[i].z * tanh_apx(q4[i].z + u.z);
            acc += v4[i].w * tanh_apx(q4[i].w + u.w);
        }
        #pragma unroll
        for (int off=16; off; off>>=1)
            acc += __shfl_xor_sync(0xffffffffu, acc, off);
        if (lane == 0) sc[w][s] = acc;
    }
    __syncwarp();

    // ---- phase 2: softmax over s (warp-private row)
    {
        float sv[4];
        #pragma unroll
        for (int i=0;i<4;i++) sv[i] = sc[w][lane + 32*i];
        float mx = fmaxf(fmaxf(sv[0],sv[1]), fmaxf(sv[2],sv[3]));
        #pragma unroll
        for (int off=16; off; off>>=1)
            mx = fmaxf(mx, __shfl_xor_sync(0xffffffffu, mx, off));
        float e[4], sum = 0.f;
        #pragma unroll
        for (int i=0;i<4;i++){ e[i] = __expf(sv[i]-mx); sum += e[i]; }
        #pragma unroll
        for (int off=16; off; off>>=1)
            sum += __shfl_xor_sync(0xffffffffu, sum, off);
        float inv = 1.f / sum;
        #pragma unroll
        for (int i=0;i<4;i++) pm[lane + 32*i][w] = e[i]*inv;
    }
    __syncthreads();

    // ---- phase 3: context c[t][d] = sum_s p[t][s] * mem[b][s][d]
    // thread owns columns d0=tid, d1=tid+256 for all 8 t-rows.
    int d0 = tid, d1 = tid + 256;
    float a0[8], a1[8];
    #pragma unroll
    for (int t=0;t<8;t++){ a0[t]=0.f; a1[t]=0.f; }
    for (int s=0; s<NL; s++){
        const float* mrow = mem + (size_t)(bb*NL + s)*ND;
        float m0v = __ldg(mrow + d0);
        float m1v = __ldg(mrow + d1);
        float4 pA = *(const float4*)&pm[s][0];
        float4 pB = *(const float4*)&pm[s][4];
        a0[0]+=pA.x*m0v; a1[0]+=pA.x*m1v;
        a0[1]+=pA.y*m0v; a1[1]+=pA.y*m1v;
        a0[2]+=pA.z*m0v; a1[2]+=pA.z*m1v;
        a0[3]+=pA.w*m0v; a1[3]+=pA.w*m1v;
        a0[4]+=pB.x*m0v; a1[4]+=pB.x*m1v;
        a0[5]+=pB.y*m0v; a1[5]+=pB.y*m1v;
        a0[6]+=pB.z*m0v; a1[6]+=pB.z*m1v;
        a0[7]+=pB.w*m0v; a1[7]+=pB.w*m1v;
    }
    #pragma unroll
    for (int t=0;t<8;t++){
        float* crow = cO + (size_t)(bb*NL + t0 + t)*ND;
        crow[d0] = a0[t];
        crow[d1] = a1[t];
    }
}

// ============================================================
// Output GEMM with on-the-fly mixing:
// out[4096,512] = Amix[4096,1024] @ Wout[1024,512] + bout
//   Amix[:,k<512]  = (1-m)*c1 + m*c2
//   Amix[:,k>=512] = (1-m)*new_obs + m*current
// (valid because a1, a2 share Wout: the mix is linear)
// ============================================================
__global__ void __launch_bounds__(256) out_gemm(
    const float* __restrict__ no, const float* __restrict__ cur,
    const float* __restrict__ Wout, const float* __restrict__ bout,
    const float* __restrict__ mix, float* __restrict__ Cout)
{
    __shared__ float As[16][68];
    __shared__ float Bs[16][64];
    const int K = 2*ND;
    int tid = threadIdx.x;
    int m0 = blockIdx.x*64, n0 = blockIdx.y*64;
    int tx = tid & 15, ty = tid >> 4;
    int lr = tid >> 2, lk = (tid & 3) * 4;
    float mv = __ldg(mix);

    float acc[4][4];
    #pragma unroll
    for (int i=0;i<4;i++)
        #pragma unroll
        for (int j=0;j<4;j++) acc[i][j]=0.f;

    for (int k0=0; k0<K; k0+=16){
        int kk = k0 + lk;
        const float* p1; const float* p2; int col;
        if (kk < ND){ p1 = g_c1; p2 = g_c2; col = kk; }
        else        { p1 = no;   p2 = cur;  col = kk - ND; }
        float4 x1 = *(const float4*)(p1 + (size_t)(m0+lr)*ND + col);
        float4 x2 = *(const float4*)(p2 + (size_t)(m0+lr)*ND + col);
        float4 av;
        av.x = x1.x + mv*(x2.x - x1.x);
        av.y = x1.y + mv*(x2.y - x1.y);
        av.z = x1.z + mv*(x2.z - x1.z);
        av.w = x1.w + mv*(x2.w - x1.w);
        float4 wv = *(const float4*)(Wout + (size_t)(k0+ty)*ND + n0 + tx*4);
        As[lk+0][lr]=av.x; As[lk+1][lr]=av.y; As[lk+2][lr]=av.z; As[lk+3][lr]=av.w;
        *(float4*)&Bs[ty][tx*4] = wv;
        __syncthreads();
        #pragma unroll
        for (int k=0;k<16;k++){
            float4 a = *(const float4*)&As[k][ty*4];
            float4 b = *(const float4*)&Bs[k][tx*4];
            acc[0][0]+=a.x*b.x; acc[0][1]+=a.x*b.y; acc[0][2]+=a.x*b.z; acc[0][3]+=a.x*b.w;
            acc[1][0]+=a.y*b.x; acc[1][1]+=a.y*b.y; acc[1][2]+=a.y*b.z; acc[1][3]+=a.y*b.w;
            acc[2][0]+=a.z*b.x; acc[2][1]+=a.z*b.y; acc[2][2]+=a.z*b.z; acc[2][3]+=a.z*b.w;
            acc[3][0]+=a.w*b.x; acc[3][1]+=a.w*b.y; acc[3][2]+=a.w*b.z; acc[3][3]+=a.w*b.w;
        }
        __syncthreads();
    }

    float b0=bout[n0+tx*4+0], b1=bout[n0+tx*4+1];
    float b2=bout[n0+tx*4+2], b3=bout[n0+tx*4+3];
    #pragma unroll
    for (int i=0;i<4;i++){
        float4 r;
        r.x=acc[i][0]+b0; r.y=acc[i][1]+b1; r.z=acc[i][2]+b2; r.w=acc[i][3]+b3;
        *(float4*)(Cout + (size_t)(m0+ty*4+i)*ND + n0 + tx*4) = r;
    }
}

extern "C" void kernel_launch(void* const* d_in, const int* in_sizes, int n_in,
                              void* d_out, int out_size)
{
    const float* cur  = (const float*)d_in[0];  // current_sotw [32,128,512]
    const float* no   = (const float*)d_in[1];  // new_obs      [32,128,512]
    const float* Wq   = (const float*)d_in[2];  // [512,512]
    const float* bq   = (const float*)d_in[3];  // [512]
    const float* Wc   = (const float*)d_in[4];  // [512,512]
    const float* v    = (const float*)d_in[5];  // [512]
    const float* Wout = (const float*)d_in[6];  // [1024,512]
    const float* bout = (const float*)d_in[7];  // [512]
    const float* mix  = (const float*)d_in[8];  // [1]
    float* out = (float*)d_out;                 // [32,128,512] fp32

    dim3 gg(NROWS/64, ND/64);  // (64, 8)

    proj_gemm<<<gg, 256>>>(no,  Wq, bq,      0);  // wq_new
    proj_gemm<<<gg, 256>>>(cur, Wq, bq,      1);  // wq_cur
    proj_gemm<<<gg, 256>>>(no,  Wc, nullptr, 2);  // uh_new
    proj_gemm<<<gg, 256>>>(cur, Wc, nullptr, 3);  // uh_cur

    attn_kernel<<<dim3(NL/8, NB, 2), 256>>>(cur, no, v);

    out_gemm<<<gg, 256>>>(no, cur, Wout, bout, mix, out);
}

// round 8
// speedup vs baseline: 1.5357x; 1.5357x over previous
#include <cuda_runtime.h>
#include <cuda_bf16.h>
#include <cstdint>

#define NB 32
#define NL 128
#define ND 512
#define NROWS (NB*NL)   // 4096

// ================= scratch (static device arrays) =================
// NOTE: these are ONLY ever referenced from device code (GB300 ATS makes
// host-passed __device__ symbols silently write host memory instead).
__device__ float g_wq_new[NROWS*ND];
__device__ float g_wq_cur[NROWS*ND];
__device__ float g_uh_new[NROWS*ND];
__device__ float g_uh_cur[NROWS*ND];
__device__ float g_c1[NROWS*ND];
__device__ float g_c2[NROWS*ND];

__device__ __nv_bfloat16 g_no_hi [NROWS*ND];
__device__ __nv_bfloat16 g_no_lo [NROWS*ND];
__device__ __nv_bfloat16 g_cur_hi[NROWS*ND];
__device__ __nv_bfloat16 g_cur_lo[NROWS*ND];
__device__ __nv_bfloat16 g_Wqt_hi[ND*ND];      // Wq^T  [N=512][K=512]
__device__ __nv_bfloat16 g_Wqt_lo[ND*ND];
__device__ __nv_bfloat16 g_Wct_hi[ND*ND];
__device__ __nv_bfloat16 g_Wct_lo[ND*ND];
__device__ __nv_bfloat16 g_Wot_hi[ND*2*ND];    // Wout^T [N=512][K=1024]
__device__ __nv_bfloat16 g_Wot_lo[ND*2*ND];
__device__ __nv_bfloat16 g_amix_hi[NROWS*2*ND];// mixed A for out gemm [4096][1024]
__device__ __nv_bfloat16 g_amix_lo[NROWS*2*ND];

// ================= helpers =================
__device__ __forceinline__ uint32_t smem_u32(const void* p){
    uint32_t a;
    asm("{ .reg .u64 t; cvta.to.shared.u64 t, %1; cvt.u32.u64 %0, t; }" : "=r"(a) : "l"(p));
    return a;
}
__device__ __forceinline__ float tanh_apx(float x){
    float y; asm("tanh.approx.f32 %0, %1;" : "=f"(y) : "f"(x)); return y;
}
__device__ __forceinline__ void split2(float x, __nv_bfloat16& h, __nv_bfloat16& l){
    h = __float2bfloat16_rn(x);
    l = __float2bfloat16_rn(x - __bfloat162float(h));
}
__device__ __forceinline__ uint32_t lds32(uint32_t a){
    uint32_t v; asm volatile("ld.shared.b32 %0, [%1];" : "=r"(v) : "r"(a)); return v;
}
__device__ __forceinline__ void mma16816(float* c, const uint32_t* a, const uint32_t* b){
    asm volatile("mma.sync.aligned.m16n8k16.row.col.f32.bf16.bf16.f32 "
        "{%0,%1,%2,%3},{%4,%5,%6,%7},{%8,%9},{%0,%1,%2,%3};"
        : "+f"(c[0]),"+f"(c[1]),"+f"(c[2]),"+f"(c[3])
        : "r"(a[0]),"r"(a[1]),"r"(a[2]),"r"(a[3]),"r"(b[0]),"r"(b[1]));
}

// ================= convert kernels (selector-based: no __device__ symbols as host args) =================
__global__ void __launch_bounds__(256) split_kernel(const float* __restrict__ in, int which)
{
    __nv_bfloat16* hi = which ? g_cur_hi : g_no_hi;
    __nv_bfloat16* lo = which ? g_cur_lo : g_no_lo;
    int i = blockIdx.x*256 + threadIdx.x;
    float4 v = ((const float4*)in)[i];
    __nv_bfloat16 h0,l0,h1,l1,h2,l2,h3,l3;
    split2(v.x,h0,l0); split2(v.y,h1,l1); split2(v.z,h2,l2); split2(v.w,h3,l3);
    __nv_bfloat162* H = (__nv_bfloat162*)hi; __nv_bfloat162* L = (__nv_bfloat162*)lo;
    H[2*i]   = __nv_bfloat162(h0,h1); H[2*i+1] = __nv_bfloat162(h2,h3);
    L[2*i]   = __nv_bfloat162(l0,l1); L[2*i+1] = __nv_bfloat162(l2,l3);
}

// in[R][C] fp32 -> out[C][R] hi/lo bf16 (transpose+split). grid (C/32, R/32), block (32,8)
__global__ void __launch_bounds__(256) splitT_kernel(
    const float* __restrict__ in, int which, int R, int C)
{
    __nv_bfloat16 *hi, *lo;
    if      (which == 0){ hi = g_Wqt_hi; lo = g_Wqt_lo; }
    else if (which == 1){ hi = g_Wct_hi; lo = g_Wct_lo; }
    else                { hi = g_Wot_hi; lo = g_Wot_lo; }
    __shared__ float t[32][33];
    int bx = blockIdx.x*32, by = blockIdx.y*32;
    int x = threadIdx.x, y = threadIdx.y;
    #pragma unroll
    for (int i=0;i<32;i+=8)
        t[y+i][x] = in[(size_t)(by+y+i)*C + bx + x];
    __syncthreads();
    #pragma unroll
    for (int i=0;i<32;i+=8){
        float v = t[x][y+i];
        __nv_bfloat16 h,l; split2(v,h,l);
        size_t o = (size_t)(bx+y+i)*R + by + x;
        hi[o]=h; lo[o]=l;
    }
}

__global__ void __launch_bounds__(256) mix_split_kernel(
    const float* __restrict__ no, const float* __restrict__ cur, const float* __restrict__ mixp)
{
    float m = __ldg(mixp);
    int i = blockIdx.x*256 + threadIdx.x;
    int r = i >> 8;
    int col = (i & 255)*4;
    const float *p1,*p2; int sc;
    if (col < ND){ p1=g_c1; p2=g_c2; sc=col; } else { p1=no; p2=cur; sc=col-ND; }
    float4 a = *(const float4*)(p1 + (size_t)r*ND + sc);
    float4 b = *(const float4*)(p2 + (size_t)r*ND + sc);
    float4 w;
    w.x=a.x+m*(b.x-a.x); w.y=a.y+m*(b.y-a.y); w.z=a.z+m*(b.z-a.z); w.w=a.w+m*(b.w-a.w);
    __nv_bfloat16 h0,l0,h1,l1,h2,l2,h3,l3;
    split2(w.x,h0,l0); split2(w.y,h1,l1); split2(w.z,h2,l2); split2(w.w,h3,l3);
    size_t o = (size_t)r*2*ND + col;
    *(__nv_bfloat162*)(g_amix_hi+o)   = __nv_bfloat162(h0,h1);
    *(__nv_bfloat162*)(g_amix_hi+o+2) = __nv_bfloat162(h2,h3);
    *(__nv_bfloat162*)(g_amix_lo+o)   = __nv_bfloat162(l0,l1);
    *(__nv_bfloat162*)(g_amix_lo+o+2) = __nv_bfloat162(l2,l3);
}

// ================= mma.sync split-bf16 GEMM =================
// C[128,128] tile = A[M,K] @ B^T (B stored [N][K]); 3-pass hi/lo, fp32 accum.
// 8 warps: warp (wm=wid&1, wn=wid>>1) owns 64x32. BK=32.
// Single smem stage (40960 B), register prefetch of next chunk.
#define BK    32
#define LDSW  40                 // padded row length (bf16 elems): 80B stride
#define MATE  (128*LDSW)         // elems per matrix tile (5120)
#define GSMEM (4*MATE*2)         // 40960 B

__device__ __forceinline__ void gemm_body(
    const __nv_bfloat16* __restrict__ Ahi, const __nv_bfloat16* __restrict__ Alo,
    const __nv_bfloat16* __restrict__ Bhi, const __nv_bfloat16* __restrict__ Blo,
    int K, const float* __restrict__ bias, float* __restrict__ C, int ldc)
{
    extern __shared__ __nv_bfloat16 sm[];
    uint32_t sb = smem_u32(sm);
    int tid = threadIdx.x, lane = tid & 31, wid = tid >> 5;
    int wm = wid & 1, wn = wid >> 1;
    int m0 = blockIdx.x*128, n0 = blockIdx.y*128;
    int g = lane >> 2, tig = lane & 3;

    const __nv_bfloat16* gp[4] = {Ahi, Alo, Bhi, Blo};
    const int rb[4] = {m0, m0, n0, n0};

    float acc[4][4][4];
    #pragma unroll
    for (int i=0;i<4;i++)
        #pragma unroll
        for (int j=0;j<4;j++)
            #pragma unroll
            for (int k=0;k<4;k++) acc[i][j][k]=0.f;

    const int chunks = K / BK;
    uint4 stg[8];

    #pragma unroll
    for (int i=0;i<8;i++){
        const int mat = i>>1;
        int cc = tid + (i&1)*256, row = cc>>2, kc = cc&3;
        stg[i] = *(const uint4*)(gp[mat] + (size_t)(rb[mat]+row)*K + kc*8);
    }

    for (int c = 0; c < chunks; c++){
        __syncthreads();
        #pragma unroll
        for (int i=0;i<8;i++){
            const int mat = i>>1;
            int cc = tid + (i&1)*256, row = cc>>2, kc = cc&3;
            *(uint4*)(sm + mat*MATE + row*LDSW + kc*8) = stg[i];
        }
        __syncthreads();
        if (c+1 < chunks){
            int k0 = (c+1)*BK;
            #pragma unroll
            for (int i=0;i<8;i++){
                const int mat = i>>1;
                int cc = tid + (i&1)*256, row = cc>>2, kc = cc&3;
                stg[i] = *(const uint4*)(gp[mat] + (size_t)(rb[mat]+row)*K + k0 + kc*8);
            }
        }

        #pragma unroll
        for (int ks=0; ks<2; ks++){
            uint32_t ah[4][4], al[4][4], bh[4][2], bl[4][2];
            // A frags: a0=(g,2t) a1=(g+8,2t) a2=(g,2t+8) a3=(g+8,2t+8)
            #pragma unroll
            for (int mt=0;mt<4;mt++){
                uint32_t o00 = (uint32_t)((wm*64 + mt*16 + g)*LDSW + ks*16 + tig*2)*2;
                uint32_t o10 = o00 + 8*LDSW*2;
                uint32_t aH = sb + 0*MATE*2, aL = sb + 1*MATE*2;
                ah[mt][0] = lds32(aH + o00);
                ah[mt][1] = lds32(aH + o10);
                ah[mt][2] = lds32(aH + o00 + 16);
                ah[mt][3] = lds32(aH + o10 + 16);
                al[mt][0] = lds32(aL + o00);
                al[mt][1] = lds32(aL + o10);
                al[mt][2] = lds32(aL + o00 + 16);
                al[mt][3] = lds32(aL + o10 + 16);
            }
            // B frags (B^T stored [n][k]): b0=(k=2t,n=g) b1=(k=2t+8,n=g)
            #pragma unroll
            for (int nt=0;nt<4;nt++){
                uint32_t o0 = (uint32_t)((wn*32 + nt*8 + g)*LDSW + ks*16 + tig*2)*2;
                uint32_t bH = sb + 2*MATE*2, bL = sb + 3*MATE*2;
                bh[nt][0] = lds32(bH + o0);
                bh[nt][1] = lds32(bH + o0 + 16);
                bl[nt][0] = lds32(bL + o0);
                bl[nt][1] = lds32(bL + o0 + 16);
            }
            #pragma unroll
            for (int mt=0;mt<4;mt++)
                #pragma unroll
                for (int nt=0;nt<4;nt++){
                    mma16816(acc[mt][nt], ah[mt], bh[nt]);
                    mma16816(acc[mt][nt], ah[mt], bl[nt]);
                    mma16816(acc[mt][nt], al[mt], bh[nt]);
                }
        }
    }

    // epilogue: c0,c1 -> (g, 2t..2t+1); c2,c3 -> (g+8, 2t..2t+1)
    int t2 = tig*2;
    #pragma unroll
    for (int mt=0;mt<4;mt++){
        int m = m0 + wm*64 + mt*16 + g;
        #pragma unroll
        for (int nt=0;nt<4;nt++){
            int n = n0 + wn*32 + nt*8 + t2;
            float b0v = bias ? bias[n]   : 0.f;
            float b1v = bias ? bias[n+1] : 0.f;
            float2 r0; r0.x = acc[mt][nt][0] + b0v; r0.y = acc[mt][nt][1] + b1v;
            float2 r1; r1.x = acc[mt][nt][2] + b0v; r1.y = acc[mt][nt][3] + b1v;
            *(float2*)(C + (size_t)m*ldc + n)     = r0;
            *(float2*)(C + (size_t)(m+8)*ldc + n) = r1;
        }
    }
}

// proj combos: z=0: no@Wq+bq ; 1: cur@Wq+bq ; 2: no@Wc ; 3: cur@Wc
__global__ void __launch_bounds__(256,1) gemm_proj_kernel(const float* __restrict__ bq){
    int combo = blockIdx.z;
    const __nv_bfloat16 *Ah,*Al,*Bh,*Bl; const float* bias; float* C;
    switch (combo){
    case 0: Ah=g_no_hi;  Al=g_no_lo;  Bh=g_Wqt_hi; Bl=g_Wqt_lo; bias=bq;      C=g_wq_new; break;
    case 1: Ah=g_cur_hi; Al=g_cur_lo; Bh=g_Wqt_hi; Bl=g_Wqt_lo; bias=bq;      C=g_wq_cur; break;
    case 2: Ah=g_no_hi;  Al=g_no_lo;  Bh=g_Wct_hi; Bl=g_Wct_lo; bias=nullptr; C=g_uh_new; break;
    default:Ah=g_cur_hi; Al=g_cur_lo; Bh=g_Wct_hi; Bl=g_Wct_lo; bias=nullptr; C=g_uh_cur; break;
    }
    gemm_body(Ah, Al, Bh, Bl, ND, bias, C, ND);
}

__global__ void __launch_bounds__(256,1) gemm_out_kernel(const float* __restrict__ bout, float* __restrict__ out){
    gemm_body(g_amix_hi, g_amix_lo, g_Wot_hi, g_Wot_lo, 2*ND, bout, out, ND);
}

// ================= fused attention (unchanged, R1-proven) =================
__global__ void __launch_bounds__(256) attn_kernel(
    const float* __restrict__ cur, const float* __restrict__ no,
    const float* __restrict__ v)
{
    __shared__ float sc[8][128];
    __shared__ float pm[128][8];

    int dir = blockIdx.z;
    int bb  = blockIdx.y;
    int t0  = blockIdx.x * 8;
    const float* wq  = dir ? g_wq_cur : g_wq_new;
    const float* uh  = dir ? g_uh_new : g_uh_cur;
    const float* mem = dir ? no       : cur;
    float*       cO  = dir ? g_c2     : g_c1;

    int tid = threadIdx.x, w = tid >> 5, lane = tid & 31;

    float4 v4[4], q4[4];
    {
        const float* wrow = wq + (size_t)(bb*NL + t0 + w)*ND;
        #pragma unroll
        for (int i=0;i<4;i++){
            v4[i] = *(const float4*)(v    + lane*4 + 128*i);
            q4[i] = *(const float4*)(wrow + lane*4 + 128*i);
        }
    }
    for (int s=0; s<NL; s++){
        const float* urow = uh + (size_t)(bb*NL + s)*ND;
        float acc = 0.f;
        #pragma unroll
        for (int i=0;i<4;i++){
            float4 u = *(const float4*)(urow + lane*4 + 128*i);
            acc += v4[i].x * tanh_apx(q4[i].x + u.x);
            acc += v4[i].y * tanh_apx(q4[i].y + u.y);
            acc += v4[i].z * tanh_apx(q4[i].z + u.z);
            acc += v4[i].w * tanh_apx(q4[i].w + u.w);
        }
        #pragma unroll
        for (int off=16; off; off>>=1)
            acc += __shfl_xor_sync(0xffffffffu, acc, off);
        if (lane == 0) sc[w][s] = acc;
    }
    __syncwarp();

    {
        float sv[4];
        #pragma unroll
        for (int i=0;i<4;i++) sv[i] = sc[w][lane + 32*i];
        float mx = fmaxf(fmaxf(sv[0],sv[1]), fmaxf(sv[2],sv[3]));
        #pragma unroll
        for (int off=16; off; off>>=1)
            mx = fmaxf(mx, __shfl_xor_sync(0xffffffffu, mx, off));
        float e[4], sum = 0.f;
        #pragma unroll
        for (int i=0;i<4;i++){ e[i] = __expf(sv[i]-mx); sum += e[i]; }
        #pragma unroll
        for (int off=16; off; off>>=1)
            sum += __shfl_xor_sync(0xffffffffu, sum, off);
        float inv = 1.f / sum;
        #pragma unroll
        for (int i=0;i<4;i++) pm[lane + 32*i][w] = e[i]*inv;
    }
    __syncthreads();

    int d0 = tid, d1 = tid + 256;
    float a0[8], a1[8];
    #pragma unroll
    for (int t=0;t<8;t++){ a0[t]=0.f; a1[t]=0.f; }
    for (int s=0; s<NL; s++){
        const float* mrow = mem + (size_t)(bb*NL + s)*ND;
        float m0v = __ldg(mrow + d0);
        float m1v = __ldg(mrow + d1);
        float4 pA = *(const float4*)&pm[s][0];
        float4 pB = *(const float4*)&pm[s][4];
        a0[0]+=pA.x*m0v; a1[0]+=pA.x*m1v;
        a0[1]+=pA.y*m0v; a1[1]+=pA.y*m1v;
        a0[2]+=pA.z*m0v; a1[2]+=pA.z*m1v;
        a0[3]+=pA.w*m0v; a1[3]+=pA.w*m1v;
        a0[4]+=pB.x*m0v; a1[4]+=pB.x*m1v;
        a0[5]+=pB.y*m0v; a1[5]+=pB.y*m1v;
        a0[6]+=pB.z*m0v; a1[6]+=pB.z*m1v;
        a0[7]+=pB.w*m0v; a1[7]+=pB.w*m1v;
    }
    #pragma unroll
    for (int t=0;t<8;t++){
        float* crow = cO + (size_t)(bb*NL + t0 + t)*ND;
        crow[d0] = a0[t];
        crow[d1] = a1[t];
    }
}

// ================= launch =================
extern "C" void kernel_launch(void* const* d_in, const int* in_sizes, int n_in,
                              void* d_out, int out_size)
{
    const float* cur  = (const float*)d_in[0];
    const float* no   = (const float*)d_in[1];
    const float* Wq   = (const float*)d_in[2];
    const float* bq   = (const float*)d_in[3];
    const float* Wc   = (const float*)d_in[4];
    const float* v    = (const float*)d_in[5];
    const float* Wout = (const float*)d_in[6];
    const float* bout = (const float*)d_in[7];
    const float* mix  = (const float*)d_in[8];
    float* out = (float*)d_out;

    split_kernel<<<2048, 256>>>(no,  0);
    split_kernel<<<2048, 256>>>(cur, 1);
    splitT_kernel<<<dim3(ND/32, ND/32),   dim3(32,8)>>>(Wq,   0, ND,   ND);
    splitT_kernel<<<dim3(ND/32, ND/32),   dim3(32,8)>>>(Wc,   1, ND,   ND);
    splitT_kernel<<<dim3(ND/32, 2*ND/32), dim3(32,8)>>>(Wout, 2, 2*ND, ND);

    gemm_proj_kernel<<<dim3(NROWS/128, ND/128, 4), 256, GSMEM>>>(bq);

    attn_kernel<<<dim3(NL/8, NB, 2), 256>>>(cur, no, v);

    mix_split_kernel<<<NROWS*2*ND/(4*256), 256>>>(no, cur, mix);
    gemm_out_kernel<<<dim3(NROWS/128, ND/128), 256, GSMEM>>>(bout, out);
}